// round 13
// baseline (speedup 1.0000x reference)
#include <cuda_runtime.h>

// Problem constants (FullChain_58815282152074): N=4096 nodes, d=16, K=16, B=4
#define MB   1024          // nodes per batch (M)
#define NB   4             // num_batches
#define IG   4             // i's per block

// Scratch: effective bilinear weight WT[d][e][o] and effective bias
__device__ float g_WT[16 * 16 * 16];
__device__ float g_beff[16];

// ---- packed f32x2 helpers (Blackwell FFMA2) ----
__device__ __forceinline__ unsigned long long ffma2(unsigned long long a,
                                                    unsigned long long b,
                                                    unsigned long long c) {
    unsigned long long d;
    asm("fma.rn.f32x2 %0, %1, %2, %3;" : "=l"(d) : "l"(a), "l"(b), "l"(c));
    return d;
}
__device__ __forceinline__ unsigned long long pack2(float lo, float hi) {
    unsigned long long d;
    asm("mov.b64 %0, {%1, %2};"
        : "=l"(d) : "r"(__float_as_uint(lo)), "r"(__float_as_uint(hi)));
    return d;
}
__device__ __forceinline__ float2 unpack2(unsigned long long v) {
    unsigned int lo, hi;
    asm("mov.b64 {%0, %1}, %2;" : "=r"(lo), "=r"(hi) : "l"(v));
    return make_float2(__uint_as_float(lo), __uint_as_float(hi));
}

// ---------------------------------------------------------------------------
// Kernel A: fold W3@W2 into the bilinear form.
//   C[o,k]     = sum_t W3[o,t] * W2[t,k]
//   WT[d,e,o]  = sum_k C[o,k] * W_bil[k,d,e]     (stored [d][e][o])
//   beff[o]    = sum_k C[o,k]*b_bil[k] + sum_t W3[o,t]*b2[t] + b3[o]
// ---------------------------------------------------------------------------
__global__ void prep_kernel(const float* __restrict__ W_bil,
                            const float* __restrict__ b_bil,
                            const float* __restrict__ W2,
                            const float* __restrict__ b2,
                            const float* __restrict__ W3,
                            const float* __restrict__ b3) {
    __shared__ float Cs[256];
    int tid = threadIdx.x;
    {
        int o = tid >> 4, k = tid & 15;
        float s = 0.f;
#pragma unroll
        for (int t = 0; t < 16; ++t) s += W3[o * 16 + t] * W2[t * 16 + k];
        Cs[tid] = s;
    }
    __syncthreads();
    {
        int d = tid >> 4, e = tid & 15;
#pragma unroll
        for (int o = 0; o < 16; ++o) {
            float s = 0.f;
#pragma unroll
            for (int k = 0; k < 16; ++k)
                s += Cs[o * 16 + k] * W_bil[k * 256 + d * 16 + e];
            g_WT[(d * 16 + e) * 16 + o] = s;
        }
    }
    if (tid < 16) {
        int o = tid;
        float s = b3[o];
#pragma unroll
        for (int k = 0; k < 16; ++k) s += Cs[o * 16 + k] * b_bil[k];
#pragma unroll
        for (int t = 0; t < 16; ++t) s += W3[o * 16 + t] * b2[t];
        g_beff[o] = s;
    }
}

// ---------------------------------------------------------------------------
// Kernel B: one block per (b, group of IG=4 i's).  256 threads, 3 CTAs/SM.
//   OCCUPANCY BET: __launch_bounds__(256,3) caps regs at 85 (ptxas spills a
//   few T pairs) and smem is dieted to 68KB (stride-16 x rows, which are
//   conflict-free here: each quarter-warp LDS.128 phase touches 2 rows in
//   disjoint bank halves).  24 warps/SM vs 16 = +50% latency cover against
//   the LDS->FFMA dependency that dominates the 118K-cyc runtime.
//   Body is the proven R6/R12 form:
//     4 broadcast LDS.128 (x) + 16 pack2 + 32 FFMA2 (2 chains)
//     + 1 warp-contiguous STG.128 per 8 edges.
// ---------------------------------------------------------------------------
__global__ __launch_bounds__(256, 3) void edge_kernel(const float* __restrict__ nodes,
                                                      float* __restrict__ out) {
    extern __shared__ float smem[];
    float* xs  = smem;                       // [MB][16]   64KB
    float* Tsm = smem + MB * 16;             // [IG][256]   4KB
    float* sbe = Tsm + IG * 256;             // [16]

    const int tid = threadIdx.x;
    const int b   = blockIdx.x >> 8;         // 256 i-groups per batch
    const int ig  = blockIdx.x & 255;
    const int i0  = ig * IG;

    // ---- Phase 0: stage batch X into shared (plain stride-16) ----
    const float4* __restrict__ Xg = (const float4*)(nodes + (size_t)b * (MB * 16));
    float4* xs4 = (float4*)xs;
#pragma unroll
    for (int k = 0; k < 16; ++k) xs4[tid + k * 256] = Xg[tid + k * 256];
    if (tid < 16) sbe[tid] = g_beff[tid];
    __syncthreads();

    // ---- Phase 1: T for the 4 i's (tid = e*16+o) ----
    {
        float t0 = 0.f, t1 = 0.f, t2 = 0.f, t3 = 0.f;
#pragma unroll
        for (int d = 0; d < 16; ++d) {
            float w = g_WT[d * 256 + tid];
            t0 += xs[(i0 + 0) * 16 + d] * w;
            t1 += xs[(i0 + 1) * 16 + d] * w;
            t2 += xs[(i0 + 2) * 16 + d] * w;
            t3 += xs[(i0 + 3) * 16 + d] * w;
        }
        Tsm[0 * 256 + tid] = t0;
        Tsm[1 * 256 + tid] = t1;
        Tsm[2 * 256 + tid] = t2;
        Tsm[3 * 256 + tid] = t3;
    }
    __syncthreads();

    // ---- Phase 2: edges ----
    const int lane = tid & 31;
    const int warp = tid >> 5;
    const int q    = lane & 3;               // o-quad: outputs [4q, 4q+4)
    const int slot = lane >> 2;              // j-slot within warp (0..7)

    const unsigned long long bias0 = pack2(sbe[4 * q],     sbe[4 * q + 1]);
    const unsigned long long bias1 = pack2(sbe[4 * q + 2], sbe[4 * q + 3]);

    const int jb = warp * 128 + slot;
    const float* __restrict__ xbase = xs + jb * 16;

#pragma unroll 1
    for (int ii = 0; ii < IG; ++ii) {
        const int i = i0 + ii;

        // T[:, 4q..4q+4) into registers (broadcast LDS.128, conflict-free)
        unsigned long long T0[16], T1[16];
#pragma unroll
        for (int e = 0; e < 16; ++e) {
            ulonglong2 tt = *(const ulonglong2*)(Tsm + ii * 256 + e * 16 + q * 4);
            T0[e] = tt.x;
            T1[e] = tt.y;
        }

        float* __restrict__ outBase =
            out + (size_t)(b * MB + i) * (MB - 1) * 16 + q * 4;

#pragma unroll 2
        for (int jj = 0; jj < 16; ++jj) {
            const int j = jb + jj * 8;

            // x_j: 4 LDS.128 (phase = 2 rows in disjoint bank halves)
            const float* xr = xbase + jj * (8 * 16);
            float4 v0 = *(const float4*)(xr);
            float4 v1 = *(const float4*)(xr + 4);
            float4 v2 = *(const float4*)(xr + 8);
            float4 v3 = *(const float4*)(xr + 12);
            float x[16] = {v0.x, v0.y, v0.z, v0.w, v1.x, v1.y, v1.z, v1.w,
                           v2.x, v2.y, v2.z, v2.w, v3.x, v3.y, v3.z, v3.w};

            unsigned long long acc0 = bias0;
            unsigned long long acc1 = bias1;
#pragma unroll
            for (int e = 0; e < 16; ++e) {
                unsigned long long xx = pack2(x[e], x[e]);
                acc0 = ffma2(T0[e], xx, acc0);
                acc1 = ffma2(T1[e], xx, acc1);
            }

            if (j != i) {
                const int r = j - (j > i);
                float2 lo = unpack2(acc0);
                float2 hi = unpack2(acc1);
                *(float4*)(outBase + (size_t)r * 16) =
                    make_float4(lo.x, lo.y, hi.x, hi.y);
            }
        }
    }
}

extern "C" void kernel_launch(void* const* d_in, const int* in_sizes, int n_in,
                              void* d_out, int out_size) {
    const float* nodes = (const float*)d_in[0];
    const float* W_bil = (const float*)d_in[1];
    const float* b_bil = (const float*)d_in[2];
    const float* W2    = (const float*)d_in[3];
    const float* b2    = (const float*)d_in[4];
    const float* W3    = (const float*)d_in[5];
    const float* b3    = (const float*)d_in[6];
    float* out = (float*)d_out;

    const int smem_bytes = (MB * 16 + IG * 256 + 16) * (int)sizeof(float);
    static bool attr_set = false;
    if (!attr_set) {
        cudaFuncSetAttribute(edge_kernel,
                             cudaFuncAttributeMaxDynamicSharedMemorySize,
                             smem_bytes);
        attr_set = true;
    }

    prep_kernel<<<1, 256>>>(W_bil, b_bil, W2, b2, W3, b3);
    edge_kernel<<<NB * (MB / IG), 256, smem_bytes>>>(nodes, out);
}

// round 14
// speedup vs baseline: 1.4494x; 1.4494x over previous
#include <cuda_runtime.h>

// Problem constants (FullChain_58815282152074): N=4096 nodes, d=16, K=16, B=4
#define MB   1024          // nodes per batch (M)
#define NB   4             // num_batches
#define IG   4             // i's per block
#define XS_STRIDE 20       // padded floats per x-row (champion R6 layout)

// Scratch: effective bilinear weight WT[d][e][o] and effective bias
__device__ float g_WT[16 * 16 * 16];
__device__ float g_beff[16];

// ---- packed f32x2 helpers (Blackwell FFMA2) ----
__device__ __forceinline__ unsigned long long ffma2(unsigned long long a,
                                                    unsigned long long b,
                                                    unsigned long long c) {
    unsigned long long d;
    asm("fma.rn.f32x2 %0, %1, %2, %3;" : "=l"(d) : "l"(a), "l"(b), "l"(c));
    return d;
}
__device__ __forceinline__ unsigned long long pack2(float lo, float hi) {
    unsigned long long d;
    asm("mov.b64 %0, {%1, %2};"
        : "=l"(d) : "r"(__float_as_uint(lo)), "r"(__float_as_uint(hi)));
    return d;
}
__device__ __forceinline__ float2 unpack2(unsigned long long v) {
    unsigned int lo, hi;
    asm("mov.b64 {%0, %1}, %2;" : "=r"(lo), "=r"(hi) : "l"(v));
    return make_float2(__uint_as_float(lo), __uint_as_float(hi));
}

// ---------------------------------------------------------------------------
// Kernel A: fold W3@W2 into the bilinear form.
//   C[o,k]     = sum_t W3[o,t] * W2[t,k]
//   WT[d,e,o]  = sum_k C[o,k] * W_bil[k,d,e]     (stored [d][e][o])
//   beff[o]    = sum_k C[o,k]*b_bil[k] + sum_t W3[o,t]*b2[t] + b3[o]
// ---------------------------------------------------------------------------
__global__ void prep_kernel(const float* __restrict__ W_bil,
                            const float* __restrict__ b_bil,
                            const float* __restrict__ W2,
                            const float* __restrict__ b2,
                            const float* __restrict__ W3,
                            const float* __restrict__ b3) {
    __shared__ float Cs[256];
    int tid = threadIdx.x;
    {
        int o = tid >> 4, k = tid & 15;
        float s = 0.f;
#pragma unroll
        for (int t = 0; t < 16; ++t) s += W3[o * 16 + t] * W2[t * 16 + k];
        Cs[tid] = s;
    }
    __syncthreads();
    {
        int d = tid >> 4, e = tid & 15;
#pragma unroll
        for (int o = 0; o < 16; ++o) {
            float s = 0.f;
#pragma unroll
            for (int k = 0; k < 16; ++k)
                s += Cs[o * 16 + k] * W_bil[k * 256 + d * 16 + e];
            g_WT[(d * 16 + e) * 16 + o] = s;
        }
    }
    if (tid < 16) {
        int o = tid;
        float s = b3[o];
#pragma unroll
        for (int k = 0; k < 16; ++k) s += Cs[o * 16 + k] * b_bil[k];
#pragma unroll
        for (int t = 0; t < 16; ++t) s += W3[o * 16 + t] * b2[t];
        g_beff[o] = s;
    }
}

// ---------------------------------------------------------------------------
// Kernel B (champion R6 base + DUAL-STREAM ILP):
//   One block per (b, group of IG=4 i's).  256 threads, 2 CTAs/SM.
//   Phase 0/1 identical to R6 (stride-20 x staging; T per i in shared).
//   Phase 2: lane = (j-slot = lane>>2, o-quad = lane&3); T in 32 u64 regs.
//   Each jj-iteration now processes TWO j's per lane (streams A: warp's
//   first 64 rows, B: second 64 rows).  All 8 LDS.128 issue BEFORE either
//   FFMA chain in program order, and the 4 accumulator chains (2 per
//   stream) are interleaved — stream B's loads + chain hide stream A's
//   LDS latency even in an in-order schedule.  All addresses are
//   compile-time offsets (no pointer IMADs, no register rotation — the
//   failure modes of R8/R9's pipelines).
// ---------------------------------------------------------------------------
__global__ __launch_bounds__(256, 2) void edge_kernel(const float* __restrict__ nodes,
                                                      float* __restrict__ out) {
    extern __shared__ float smem[];
    float* xs  = smem;                       // [MB][XS_STRIDE]  80KB
    float* Tsm = smem + MB * XS_STRIDE;      // [IG][256]        4KB
    float* sbe = Tsm + IG * 256;             // [16]

    const int tid = threadIdx.x;
    const int b   = blockIdx.x >> 8;         // 256 i-groups per batch
    const int ig  = blockIdx.x & 255;
    const int i0  = ig * IG;

    // ---- Phase 0: stage batch X into padded shared ----
    const float4* __restrict__ Xg = (const float4*)(nodes + (size_t)b * (MB * 16));
#pragma unroll
    for (int k = 0; k < 16; ++k) {
        int idx = tid + k * 256;             // float4 index, coalesced
        float4 v = Xg[idx];
        int row = idx >> 2, c = idx & 3;
        *(float4*)(xs + row * XS_STRIDE + c * 4) = v;
    }
    if (tid < 16) sbe[tid] = g_beff[tid];
    __syncthreads();

    // ---- Phase 1: T for the 4 i's (tid = e*16+o) ----
    {
        float t0 = 0.f, t1 = 0.f, t2 = 0.f, t3 = 0.f;
#pragma unroll
        for (int d = 0; d < 16; ++d) {
            float w = g_WT[d * 256 + tid];
            t0 += xs[(i0 + 0) * XS_STRIDE + d] * w;
            t1 += xs[(i0 + 1) * XS_STRIDE + d] * w;
            t2 += xs[(i0 + 2) * XS_STRIDE + d] * w;
            t3 += xs[(i0 + 3) * XS_STRIDE + d] * w;
        }
        Tsm[0 * 256 + tid] = t0;
        Tsm[1 * 256 + tid] = t1;
        Tsm[2 * 256 + tid] = t2;
        Tsm[3 * 256 + tid] = t3;
    }
    __syncthreads();

    // ---- Phase 2: edges, dual-stream ----
    const int lane = tid & 31;
    const int warp = tid >> 5;
    const int q    = lane & 3;               // o-quad: outputs [4q, 4q+4)
    const int slot = lane >> 2;              // j-slot within warp (0..7)

    const unsigned long long bias0 = pack2(sbe[4 * q],     sbe[4 * q + 1]);
    const unsigned long long bias1 = pack2(sbe[4 * q + 2], sbe[4 * q + 3]);

    const int jb = warp * 128 + slot;        // stream A base; B = A + 64
    const float* __restrict__ xbase = xs + jb * XS_STRIDE;

#pragma unroll 1
    for (int ii = 0; ii < IG; ++ii) {
        const int i = i0 + ii;

        // T[:, 4q..4q+4) into registers (broadcast LDS.128, conflict-free)
        unsigned long long T0[16], T1[16];
#pragma unroll
        for (int e = 0; e < 16; ++e) {
            ulonglong2 tt = *(const ulonglong2*)(Tsm + ii * 256 + e * 16 + q * 4);
            T0[e] = tt.x;
            T1[e] = tt.y;
        }

        float* __restrict__ outBase =
            out + (size_t)(b * MB + i) * (MB - 1) * 16 + q * 4;

#pragma unroll 1
        for (int jj = 0; jj < 8; ++jj) {
            const int jA = jb + jj * 8;      // stream A: rows [warp*128, +64)
            const int jB = jA + 64;          // stream B: rows [+64, +128)

            // ALL loads first: stream A then stream B (8 LDS.128 total)
            const float* xrA = xbase + jj * (8 * XS_STRIDE);
            float4 a0 = *(const float4*)(xrA);
            float4 a1 = *(const float4*)(xrA + 4);
            float4 a2 = *(const float4*)(xrA + 8);
            float4 a3 = *(const float4*)(xrA + 12);
            const float* xrB = xrA + 64 * XS_STRIDE;
            float4 b0 = *(const float4*)(xrB);
            float4 b1 = *(const float4*)(xrB + 4);
            float4 b2v = *(const float4*)(xrB + 8);
            float4 b3v = *(const float4*)(xrB + 12);

            float xA[16] = {a0.x, a0.y, a0.z, a0.w, a1.x, a1.y, a1.z, a1.w,
                            a2.x, a2.y, a2.z, a2.w, a3.x, a3.y, a3.z, a3.w};
            float xB[16] = {b0.x, b0.y, b0.z, b0.w, b1.x, b1.y, b1.z, b1.w,
                            b2v.x, b2v.y, b2v.z, b2v.w, b3v.x, b3v.y, b3v.z, b3v.w};

            unsigned long long accA0 = bias0, accA1 = bias1;
            unsigned long long accB0 = bias0, accB1 = bias1;

            // interleaved chains: 4 independent FFMA2 dependency chains
#pragma unroll
            for (int e = 0; e < 16; ++e) {
                unsigned long long xxA = pack2(xA[e], xA[e]);
                accA0 = ffma2(T0[e], xxA, accA0);
                accA1 = ffma2(T1[e], xxA, accA1);
                unsigned long long xxB = pack2(xB[e], xB[e]);
                accB0 = ffma2(T0[e], xxB, accB0);
                accB1 = ffma2(T1[e], xxB, accB1);
            }

            if (jA != i) {
                const int r = jA - (jA > i);
                float2 lo = unpack2(accA0);
                float2 hi = unpack2(accA1);
                *(float4*)(outBase + (size_t)r * 16) =
                    make_float4(lo.x, lo.y, hi.x, hi.y);
            }
            if (jB != i) {
                const int r = jB - (jB > i);
                float2 lo = unpack2(accB0);
                float2 hi = unpack2(accB1);
                *(float4*)(outBase + (size_t)r * 16) =
                    make_float4(lo.x, lo.y, hi.x, hi.y);
            }
        }
    }
}

extern "C" void kernel_launch(void* const* d_in, const int* in_sizes, int n_in,
                              void* d_out, int out_size) {
    const float* nodes = (const float*)d_in[0];
    const float* W_bil = (const float*)d_in[1];
    const float* b_bil = (const float*)d_in[2];
    const float* W2    = (const float*)d_in[3];
    const float* b2    = (const float*)d_in[4];
    const float* W3    = (const float*)d_in[5];
    const float* b3    = (const float*)d_in[6];
    float* out = (float*)d_out;

    const int smem_bytes = (MB * XS_STRIDE + IG * 256 + 16) * (int)sizeof(float);
    static bool attr_set = false;
    if (!attr_set) {
        cudaFuncSetAttribute(edge_kernel,
                             cudaFuncAttributeMaxDynamicSharedMemorySize,
                             smem_bytes);
        attr_set = true;
    }

    prep_kernel<<<1, 256>>>(W_bil, b_bil, W2, b2, W3, b3);
    edge_kernel<<<NB * (MB / IG), 256, smem_bytes>>>(nodes, out);
}